// round 5
// baseline (speedup 1.0000x reference)
#include <cuda_runtime.h>
#include <math.h>

// Problem constants (fixed by the reference)
#define Bc 8
#define Sc 64
#define Nc 1024
#define Cc 16
#define Hc 128
#define Pc 10
#define MAXN 128
#define SLICE (Bc * Nc * Hc)   // floats per p-slice of g_sol

typedef unsigned long long ull;

// ---------------------------------------------------------------------------
// Device-global scratch
// ---------------------------------------------------------------------------
__device__ float      g_sol [Pc * Bc * Nc * Hc];       // [p][b][n][h] row-major (40MB)
__device__ ulonglong2 g_solt[Pc * Nc * Hc * 2];        // [p][n][h][b-pairs] transposed (40MB)
__device__ float g_logits[2][Bc * Nc];                 // double-buffered (race fix)
__device__ int   g_nbr[Nc * MAXN];
__device__ int   g_cnt[Nc];
__device__ float g_inv[Nc];

// ---------------------------------------------------------------------------
// f32x2 helpers (PTX only — ptxas won't auto-fuse)
// ---------------------------------------------------------------------------
__device__ __forceinline__ ull pk2(float lo, float hi) {
    ull r; asm("mov.b64 %0, {%1,%2};" : "=l"(r) : "f"(lo), "f"(hi)); return r;
}
__device__ __forceinline__ void upk2(ull v, float& lo, float& hi) {
    asm("mov.b64 {%0,%1}, %2;" : "=f"(lo), "=f"(hi) : "l"(v));
}
__device__ __forceinline__ ull fma2(ull a, ull b, ull c) {
    ull d; asm("fma.rn.f32x2 %0, %1, %2, %3;" : "=l"(d) : "l"(a), "l"(b), "l"(c)); return d;
}

__device__ __forceinline__ float silu_f(float v) { return v / (1.0f + expf(-v)); }

// 128-thread block: reduce (a,b) to block-wide sums, broadcast
__device__ __forceinline__ void red2_128(float& a, float& b, float* sm) {
#pragma unroll
    for (int o = 16; o > 0; o >>= 1) {
        a += __shfl_xor_sync(0xffffffffu, a, o);
        b += __shfl_xor_sync(0xffffffffu, b, o);
    }
    int w = threadIdx.x >> 5;
    if ((threadIdx.x & 31) == 0) { sm[w] = a; sm[4 + w] = b; }
    __syncthreads();
    a = sm[0] + sm[1] + sm[2] + sm[3];
    b = sm[4] + sm[5] + sm[6] + sm[7];
    __syncthreads();
}

// ---------------------------------------------------------------------------
// CSR build: one warp per adjacency row (deterministic via ballot/popc)
// ---------------------------------------------------------------------------
__global__ void build_csr_kernel(const float* __restrict__ adj) {
    int m = blockIdx.x * (blockDim.x >> 5) + (threadIdx.x >> 5);
    int lane = threadIdx.x & 31;
    if (m >= Nc) return;
    float rsum = 0.0f;
    int cnt = 0;
    for (int base = 0; base < Nc; base += 32) {
        float a = adj[m * Nc + base + lane];
        rsum += a;
        unsigned mask = __ballot_sync(0xffffffffu, a > 0.0f);
        if (a > 0.0f) {
            int pos = cnt + __popc(mask & ((1u << lane) - 1u));
            if (pos < MAXN) g_nbr[m * MAXN + pos] = base + lane;
        }
        cnt += __popc(mask);
    }
#pragma unroll
    for (int o = 16; o > 0; o >>= 1) rsum += __shfl_xor_sync(0xffffffffu, rsum, o);
    if (lane == 0) {
        g_cnt[m] = cnt < MAXN ? cnt : MAXN;
        g_inv[m] = 1.0f / (rsum + 1e-8f);
    }
}

// ---------------------------------------------------------------------------
// Encoder: z0 -> g_sol[0] (row-major) + g_solt[0] (transposed) + logits buf 0
// grid (N, B), 128 threads
// ---------------------------------------------------------------------------
__global__ void enc_kernel(const float* __restrict__ x,
                           const float* __restrict__ w, const float* __restrict__ bb,
                           const float* __restrict__ g, const float* __restrict__ beta,
                           const float* __restrict__ attn_w,
                           const float* __restrict__ attn_b) {
    int n = blockIdx.x, b = blockIdx.y, j = threadIdx.x;
    __shared__ float xr[Cc];
    __shared__ float red[8];
    if (j < Cc) xr[j] = x[((size_t)b * Sc * Nc + n) * Cc + j];
    __syncthreads();
    float u = bb[j];
#pragma unroll
    for (int c = 0; c < Cc; c++) u += xr[c] * w[c * Hc + j];
    float s1 = u, s2 = u * u;
    red2_128(s1, s2, red);
    float mean = s1 * (1.0f / Hc);
    float var  = s2 * (1.0f / Hc) - mean * mean;
    float ln = (u - mean) * rsqrtf(var + 1e-5f) * g[j] + beta[j];
    float z = silu_f(ln);
    g_sol[((size_t)b * Nc + n) * Hc + j] = z;
    ((float*)g_solt)[(((size_t)n * Hc + j) << 3) + b] = z;
    float la = z * attn_w[j], lz = 0.0f;
    red2_128(la, lz, red);
    if (j == 0) g_logits[0][b * Nc + n] = la + attn_b[0];
}

// ---------------------------------------------------------------------------
// One Euler step. 2 nodes x 8 batches per block, block (128,2).
// Fused: softmax stats (per-warp redundant, from logits buf (p-1)&1) +
// dyn GEMMs (f32x2) + diffusion (transposed gathers) + norm clamp +
// logits epilogue into buf p&1. grid (Nc/2).
// ---------------------------------------------------------------------------
__global__ void __launch_bounds__(256)
step_kernel(const float* __restrict__ w1, const float* __restrict__ b1,
            const float* __restrict__ g,  const float* __restrict__ beta,
            const float* __restrict__ w2, const float* __restrict__ b2,
            const float* __restrict__ diff_scale,
            const float* __restrict__ time_scale,
            const float* __restrict__ attn_w,
            const float* __restrict__ attn_b, int p) {
    int j = threadIdx.x;            // 0..127 (feature / column)
    int y = threadIdx.y;            // 0..1   (node slab)
    int m = blockIdx.x * 2 + y;
    int tid = y * 128 + j;
    int gw = tid >> 5;              // global warp 0..7 -> batch for softmax stats
    int lane = j & 31;
    int lwid = j >> 5;              // warp within slab 0..3

    const float* lg_in  = g_logits[(p - 1) & 1];
    float*       lg_out = g_logits[p & 1];

    __shared__ ulonglong2 sp[2][Hc][2];        // paired state / hidden, k-major
    __shared__ float hs[2][8][Hc + 4];
    __shared__ float redq[2][4][8];
    __shared__ float smean[2][8], srstd[2][8];
    __shared__ float smax8[8], ssum8[8];
    __shared__ int   nidx[2][MAXN];
    __shared__ ulonglong2 coefp[2][MAXN][2];

    // ---- fused softmax stats: warp gw handles batch gw over all 1024 logits
    {
        float mx = -3.402823466e38f;
        for (int n = lane; n < Nc; n += 32) mx = fmaxf(mx, lg_in[gw * Nc + n]);
#pragma unroll
        for (int o = 16; o > 0; o >>= 1) mx = fmaxf(mx, __shfl_xor_sync(0xffffffffu, mx, o));
        float sum = 0.0f;
        for (int n = lane; n < Nc; n += 32) sum += expf(lg_in[gw * Nc + n] - mx);
#pragma unroll
        for (int o = 16; o > 0; o >>= 1) sum += __shfl_xor_sync(0xffffffffu, sum, o);
        if (lane == 0) { smax8[gw] = mx; ssum8[gw] = sum; }
    }

    // ---- own state (transposed layout: 8 batches contiguous at (m, j))
    const ulonglong2* st_in = g_solt + (size_t)(p - 1) * Nc * Hc * 2;
    ulonglong2 t0 = st_in[(((size_t)m * Hc + j) << 1) + 0];
    ulonglong2 t1 = st_in[(((size_t)m * Hc + j) << 1) + 1];
    sp[y][j][0] = t0; sp[y][j][1] = t1;
    float sv[8];
    upk2(t0.x, sv[0], sv[1]); upk2(t0.y, sv[2], sv[3]);
    upk2(t1.x, sv[4], sv[5]); upk2(t1.y, sv[6], sv[7]);

    int   cnt = g_cnt[m];
    float inv = g_inv[m];
    __syncthreads();   // smax/ssum + sp ready

    // ---- neighbor coefficients: coef[b] = exp(l-max)/sum * inv
    if (j < cnt) {
        int nb = g_nbr[m * MAXN + j];
        nidx[y][j] = nb;
        float e[8];
#pragma unroll
        for (int r = 0; r < 8; r++)
            e[r] = expf(lg_in[r * Nc + nb] - smax8[r]) / ssum8[r] * inv;
        coefp[y][j][0] = make_ulonglong2(pk2(e[0], e[1]), pk2(e[2], e[3]));
        coefp[y][j][1] = make_ulonglong2(pk2(e[4], e[5]), pk2(e[6], e[7]));
    }

    // ---- dyn GEMM1: u = s @ W1 + b1
    float bj = b1[j];
    ull acc0 = pk2(bj, bj), acc1 = acc0, acc2 = acc0, acc3 = acc0;
#pragma unroll 4
    for (int k = 0; k < Hc; k++) {
        float w = w1[k * Hc + j];
        ull wp = pk2(w, w);
        ulonglong2 z0 = sp[y][k][0];
        ulonglong2 z1 = sp[y][k][1];
        acc0 = fma2(z0.x, wp, acc0);
        acc1 = fma2(z0.y, wp, acc1);
        acc2 = fma2(z1.x, wp, acc2);
        acc3 = fma2(z1.y, wp, acc3);
    }
    float u[8];
    upk2(acc0, u[0], u[1]); upk2(acc1, u[2], u[3]);
    upk2(acc2, u[4], u[5]); upk2(acc3, u[6], u[7]);
#pragma unroll
    for (int r = 0; r < 8; r++) hs[y][r][j] = u[r];
    __syncthreads();

    // ---- LN stats (per slab: 4 warps x 2 rows)
#pragma unroll
    for (int rr = 0; rr < 2; rr++) {
        int r = lwid * 2 + rr;
        float s1 = 0.0f, s2 = 0.0f;
#pragma unroll
        for (int kk = lane; kk < Hc; kk += 32) {
            float v = hs[y][r][kk];
            s1 += v; s2 += v * v;
        }
#pragma unroll
        for (int o = 16; o > 0; o >>= 1) {
            s1 += __shfl_xor_sync(0xffffffffu, s1, o);
            s2 += __shfl_xor_sync(0xffffffffu, s2, o);
        }
        if (lane == 0) {
            float mean = s1 * (1.0f / Hc);
            float var  = s2 * (1.0f / Hc) - mean * mean;
            smean[y][r] = mean;
            srstd[y][r] = rsqrtf(var + 1e-5f);
        }
    }
    __syncthreads();

    float gj = g[j], betaj = beta[j];
    float hv[8];
#pragma unroll
    for (int r = 0; r < 8; r++)
        hv[r] = silu_f((u[r] - smean[y][r]) * srstd[y][r] * gj + betaj);
    sp[y][j][0] = make_ulonglong2(pk2(hv[0], hv[1]), pk2(hv[2], hv[3]));
    sp[y][j][1] = make_ulonglong2(pk2(hv[4], hv[5]), pk2(hv[6], hv[7]));
    __syncthreads();

    // ---- dyn GEMM2: d = h @ W2 + b2, tanh
    float b2j = b2[j];
    ull d0 = pk2(b2j, b2j), d1 = d0, d2 = d0, d3 = d0;
#pragma unroll 4
    for (int k = 0; k < Hc; k++) {
        float w = w2[k * Hc + j];
        ull wp = pk2(w, w);
        ulonglong2 z0 = sp[y][k][0];
        ulonglong2 z1 = sp[y][k][1];
        d0 = fma2(z0.x, wp, d0);
        d1 = fma2(z0.y, wp, d1);
        d2 = fma2(z1.x, wp, d2);
        d3 = fma2(z1.y, wp, d3);
    }
    float dd[8];
    upk2(d0, dd[0], dd[1]); upk2(d1, dd[2], dd[3]);
    upk2(d2, dd[4], dd[5]); upk2(d3, dd[6], dd[7]);
    float dyn[8];
#pragma unroll
    for (int r = 0; r < 8; r++) dyn[r] = tanhf(dd[r]);

    // ---- diffusion: sum over neighbors of coef * s (paired loads)
    ull dv0 = 0, dv1 = 0, dv2 = 0, dv3 = 0;
    for (int k = 0; k < cnt; k++) {
        int nb = nidx[y][k];
        const ulonglong2* q = &st_in[(((size_t)nb * Hc + j) << 1)];
        ulonglong2 s0 = q[0], s1 = q[1];
        ulonglong2 c0 = coefp[y][k][0], c1 = coefp[y][k][1];
        dv0 = fma2(s0.x, c0.x, dv0);
        dv1 = fma2(s0.y, c0.y, dv1);
        dv2 = fma2(s1.x, c1.x, dv2);
        dv3 = fma2(s1.y, c1.y, dv3);
    }
    float dvf[8];
    upk2(dv0, dvf[0], dvf[1]); upk2(dv1, dvf[2], dvf[3]);
    upk2(dv2, dvf[4], dvf[5]); upk2(dv3, dvf[6], dvf[7]);

    float ds = diff_scale[0], ts = time_scale[0];
    float dx[8];
#pragma unroll
    for (int r = 0; r < 8; r++) dx[r] = ts * (dyn[r] + dvf[r] * ds);

    // ---- per-row norm clamp
    float q[8];
#pragma unroll
    for (int r = 0; r < 8; r++) q[r] = dx[r] * dx[r];
#pragma unroll
    for (int o = 16; o > 0; o >>= 1)
#pragma unroll
        for (int r = 0; r < 8; r++) q[r] += __shfl_xor_sync(0xffffffffu, q[r], o);
    if (lane == 0) {
#pragma unroll
        for (int r = 0; r < 8; r++) redq[y][lwid][r] = q[r];
    }
    __syncthreads();

    float o8[8];
#pragma unroll
    for (int r = 0; r < 8; r++) {
        float nr = sqrtf(redq[y][0][r] + redq[y][1][r] + redq[y][2][r] + redq[y][3][r]);
        float sc = fminf(10.0f / (nr + 1e-8f), 1.0f);
        o8[r] = sv[r] + (dx[r] * sc) * 7.0f;
    }

    // ---- stores: row-major + transposed
    float* s_out = g_sol + (size_t)p * SLICE;
#pragma unroll
    for (int r = 0; r < 8; r++) s_out[((size_t)r * Nc + m) * Hc + j] = o8[r];
    ulonglong2* st_out = g_solt + (size_t)p * Nc * Hc * 2;
    st_out[(((size_t)m * Hc + j) << 1) + 0] = make_ulonglong2(pk2(o8[0], o8[1]), pk2(o8[2], o8[3]));
    st_out[(((size_t)m * Hc + j) << 1) + 1] = make_ulonglong2(pk2(o8[4], o8[5]), pk2(o8[6], o8[7]));

    // ---- fused logits for next step's softmax (write buffer p&1)
    float aw = attn_w[j];
    float la[8];
#pragma unroll
    for (int r = 0; r < 8; r++) la[r] = o8[r] * aw;
#pragma unroll
    for (int o = 16; o > 0; o >>= 1)
#pragma unroll
        for (int r = 0; r < 8; r++) la[r] += __shfl_xor_sync(0xffffffffu, la[r], o);
    __syncthreads();   // all redq reads done before overwrite
    if (lane == 0) {
#pragma unroll
        for (int r = 0; r < 8; r++) redq[y][lwid][r] = la[r];
    }
    __syncthreads();
    if (j < 8)
        lg_out[j * Nc + m] = redq[y][0][j] + redq[y][1][j] + redq[y][2][j] + redq[y][3][j]
                           + attn_b[0];
}

// ---------------------------------------------------------------------------
// Interp + decoder. 16 time-rows per block, block (128,2), grid (Nc, Bc, 4).
// f32x2 GEMM1, k-major pairs; f32x2 pred epilogue on 128 pair-threads.
// ---------------------------------------------------------------------------
__global__ void __launch_bounds__(256)
decode_kernel(const float* __restrict__ w1, const float* __restrict__ b1,
              const float* __restrict__ g,  const float* __restrict__ beta,
              const float* __restrict__ w2, const float* __restrict__ b2,
              float* __restrict__ pred, float* __restrict__ interp) {
    int j = threadIdx.x, y = threadIdx.y;
    int n = blockIdx.x, b = blockIdx.y, sg = blockIdx.z;
    int tid = y * 128 + j;
    int gw = tid >> 5, lane = j & 31;

    __shared__ ulonglong2 zsp[Hc][4];    // [k][4] = 16 rows as pairs
    __shared__ float hs[16][Hc + 4];
    __shared__ float smean[16], srstd[16];

    // ---- interp with deduped slice loads (ic nondecreasing over r)
    size_t base = ((size_t)b * Nc + n) * Hc + j;
    float zv[8];
    int ic_prev = -9;
    float a0 = 0.0f, a1 = 0.0f;
#pragma unroll
    for (int r = 0; r < 8; r++) {
        int si = sg * 16 + y * 8 + r;
        int ic = (si + 6) / 7;
        if (ic < 1) ic = 1;
        if (ic != ic_prev) {
            if (ic == ic_prev + 1) { a0 = a1; a1 = g_sol[(size_t)ic * SLICE + base]; }
            else { a0 = g_sol[(size_t)(ic - 1) * SLICE + base];
                   a1 = g_sol[(size_t)ic * SLICE + base]; }
            ic_prev = ic;
        }
        float alpha = (float)(si - 7 * (ic - 1)) * (1.0f / 7.0f);
        zv[r] = (1.0f - alpha) * a0 + alpha * a1;
        if (interp) interp[(((size_t)si * Bc + b) * Nc + n) * Hc + j] = zv[r];
    }
    zsp[j][y * 2 + 0] = make_ulonglong2(pk2(zv[0], zv[1]), pk2(zv[2], zv[3]));
    zsp[j][y * 2 + 1] = make_ulonglong2(pk2(zv[4], zv[5]), pk2(zv[6], zv[7]));
    __syncthreads();

    // ---- GEMM1: u = z @ dec_w1 + b1 for this slab's 8 rows
    float bj = b1[j];
    ull acc0 = pk2(bj, bj), acc1 = acc0, acc2 = acc0, acc3 = acc0;
#pragma unroll 4
    for (int k = 0; k < Hc; k++) {
        float w = w1[k * Hc + j];
        ull wp = pk2(w, w);
        ulonglong2 z0 = zsp[k][y * 2 + 0];
        ulonglong2 z1 = zsp[k][y * 2 + 1];
        acc0 = fma2(z0.x, wp, acc0);
        acc1 = fma2(z0.y, wp, acc1);
        acc2 = fma2(z1.x, wp, acc2);
        acc3 = fma2(z1.y, wp, acc3);
    }
    float u[8];
    upk2(acc0, u[0], u[1]); upk2(acc1, u[2], u[3]);
    upk2(acc2, u[4], u[5]); upk2(acc3, u[6], u[7]);
#pragma unroll
    for (int r = 0; r < 8; r++) hs[y * 8 + r][j] = u[r];
    __syncthreads();

    // ---- LN stats: 8 warps x 2 rows
#pragma unroll
    for (int rr = 0; rr < 2; rr++) {
        int r = gw * 2 + rr;
        float s1 = 0.0f, s2 = 0.0f;
#pragma unroll
        for (int kk = lane; kk < Hc; kk += 32) {
            float v = hs[r][kk];
            s1 += v; s2 += v * v;
        }
#pragma unroll
        for (int o = 16; o > 0; o >>= 1) {
            s1 += __shfl_xor_sync(0xffffffffu, s1, o);
            s2 += __shfl_xor_sync(0xffffffffu, s2, o);
        }
        if (lane == 0) {
            float mean = s1 * (1.0f / Hc);
            float var  = s2 * (1.0f / Hc) - mean * mean;
            smean[r] = mean;
            srstd[r] = rsqrtf(var + 1e-5f);
        }
    }
    __syncthreads();

    float gj = g[j], betaj = beta[j];
    float hv[8];
#pragma unroll
    for (int r = 0; r < 8; r++) {
        int row = y * 8 + r;
        hv[r] = silu_f((u[r] - smean[row]) * srstd[row] * gj + betaj);
    }
    zsp[j][y * 2 + 0] = make_ulonglong2(pk2(hv[0], hv[1]), pk2(hv[2], hv[3]));
    zsp[j][y * 2 + 1] = make_ulonglong2(pk2(hv[4], hv[5]), pk2(hv[6], hv[7]));
    __syncthreads();

    // ---- pred: h @ dec_w2 + b2; 128 pair-threads, rows (2q, 2q+1)
    if (pred && tid < 128) {
        int qq = tid >> 4, c = tid & 15;
        float bc = b2[c];
        ull accp = pk2(bc, bc);
        const ull* hp = (const ull*)zsp;   // [k][8] row-pairs
#pragma unroll 4
        for (int k = 0; k < Hc; k++) {
            float w = w2[k * Cc + c];
            accp = fma2(hp[k * 8 + qq], pk2(w, w), accp);
        }
        float p0, p1;
        upk2(accp, p0, p1);
        int si0 = sg * 16 + 2 * qq;
        pred[(((size_t)b * Sc + si0)     * Nc + n) * Cc + c] = p0;
        pred[(((size_t)b * Sc + si0 + 1) * Nc + n) * Cc + c] = p1;
    }
}

// ---------------------------------------------------------------------------
// Launch
// ---------------------------------------------------------------------------
extern "C" void kernel_launch(void* const* d_in, const int* in_sizes, int n_in,
                              void* d_out, int out_size) {
    const float* x        = (const float*)d_in[0];
    const float* adj      = (const float*)d_in[1];
    const float* enc_w    = (const float*)d_in[2];
    const float* enc_b    = (const float*)d_in[3];
    const float* enc_g    = (const float*)d_in[4];
    const float* enc_beta = (const float*)d_in[5];
    const float* dyn_w1   = (const float*)d_in[6];
    const float* dyn_b1   = (const float*)d_in[7];
    const float* dyn_g    = (const float*)d_in[8];
    const float* dyn_beta = (const float*)d_in[9];
    const float* dyn_w2   = (const float*)d_in[10];
    const float* dyn_b2   = (const float*)d_in[11];
    const float* attn_w   = (const float*)d_in[12];
    const float* attn_b   = (const float*)d_in[13];
    const float* diff_sc  = (const float*)d_in[14];
    const float* time_sc  = (const float*)d_in[15];
    const float* dec_w1   = (const float*)d_in[16];
    const float* dec_b1   = (const float*)d_in[17];
    const float* dec_g    = (const float*)d_in[18];
    const float* dec_beta = (const float*)d_in[19];
    const float* dec_w2   = (const float*)d_in[20];
    const float* dec_b2   = (const float*)d_in[21];

    float* out = (float*)d_out;
    const long long PRED_SZ   = (long long)Bc * Sc * Nc * Cc;   //  8388608
    const long long INTERP_SZ = (long long)Sc * Bc * Nc * Hc;   // 67108864
    float* pred_ptr = nullptr;
    float* interp_ptr = nullptr;
    long long osz = (long long)out_size;
    if (osz >= PRED_SZ + INTERP_SZ) { pred_ptr = out; interp_ptr = out + PRED_SZ; }
    else if (osz == INTERP_SZ)      { interp_ptr = out; }
    else                            { pred_ptr = out; }

    build_csr_kernel<<<Nc / 8, 256>>>(adj);
    enc_kernel<<<dim3(Nc, Bc), 128>>>(x, enc_w, enc_b, enc_g, enc_beta,
                                      attn_w, attn_b);

    for (int p = 1; p < Pc; p++) {
        step_kernel<<<Nc / 2, dim3(128, 2)>>>(dyn_w1, dyn_b1, dyn_g, dyn_beta,
                                              dyn_w2, dyn_b2, diff_sc, time_sc,
                                              attn_w, attn_b, p);
    }

    decode_kernel<<<dim3(Nc, Bc, 4), dim3(128, 2)>>>(dec_w1, dec_b1, dec_g, dec_beta,
                                                     dec_w2, dec_b2,
                                                     pred_ptr, interp_ptr);
}